// round 14
// baseline (speedup 1.0000x reference)
#include <cuda_runtime.h>

// scratch (static device globals - no allocation allowed)
__device__ float2 d_xsel[2048 * 512];   // fwd DFT modes: ch 0..1023 = q, 1024..2047 = k
__device__ float2 d_z[1024 * 512];      // xqkvw / 16384, per (b,h,o) channel

// ---------------------------------------------------------------------------
// Kernel 1: truncated forward DFT (ortho).  One CTA per channel (2048 CTAs).
// X[k0,k1,k2] = (1/256) * sum_{n0,n1,n2} x[n0,n1,n2] e^{-2pi i(k0 n0/32 + k1 n1/32 + k2 n2/64)}
// separable: dim2 (64->8, real-input symmetry halves it) -> dim1 (32->8) -> dim0 (32->8),
// processed in 4 chunks of 8 n0-planes.
// ---------------------------------------------------------------------------
__global__ void __launch_bounds__(256) fwd_dft_kernel(const float* __restrict__ q,
                                                      const float* __restrict__ kin)
{
    extern __shared__ float sm[];
    float*  xs  = sm;                       // 256 rows x 65 (padded) = 16640 floats
    float2* T   = (float2*)(sm + 16640);    // 256 x 9 (padded)      = 2304 float2
    float2* B1  = T + 2304;                 // 8 x 64                = 512 float2
    float2* w64 = B1 + 512;                 // 64 x 8 twiddles       = 512 float2 (16B aligned)
    float2* w32 = w64 + 512;                // 32 x 8 twiddles       = 256 float2

    const int tid = threadIdx.x;
    const int c   = blockIdx.x;
    const float* src = (c < 1024) ? (q + (size_t)c * 65536)
                                  : (kin + (size_t)(c - 1024) * 65536);

    // twiddles: w64[n*8+k] = exp(-2pi i n k / 64), w32[n*8+k] = exp(-2pi i n k / 32)
    {
        float s, co;
        int n = tid >> 3, k = tid & 7;
        sincospif((float)(n * k) * (1.0f / 32.0f), &s, &co);
        w64[tid] = make_float2(co, -s);
        int t2 = tid + 256;
        n = t2 >> 3; k = t2 & 7;
        sincospif((float)(n * k) * (1.0f / 32.0f), &s, &co);
        w64[t2] = make_float2(co, -s);
        n = tid >> 3; k = tid & 7;
        sincospif((float)(n * k) * (1.0f / 16.0f), &s, &co);
        w32[tid] = make_float2(co, -s);
    }
    __syncthreads();

    const int m = tid & 63;     // k1*8 + k2
    const int g = tid >> 6;     // owns k0 = g and g+4
    float aAr = 0.f, aAi = 0.f, aBr = 0.f, aBi = 0.f;

    for (int chunk = 0; chunk < 4; ++chunk) {
        // load 8 n0-planes (16384 floats) coalesced into padded smem rows
        const float* s0 = src + chunk * 16384;
        for (int i = tid * 4; i < 16384; i += 1024) {
            float4 v = *(const float4*)(s0 + i);
            int row = i >> 6, col = i & 63;
            float* d = xs + row * 65 + col;
            d[0] = v.x; d[1] = v.y; d[2] = v.z; d[3] = v.w;
        }
        __syncthreads();

        // stage A: per row (n0,n1): 8 k2 modes over n2, exploiting real-input
        // symmetry: pair n2 with 64-n2 (cos even, sin odd about n2=32).
        // Twiddles fetched as float4 (2 complex pairs) -> 4 LDS.128 per n2.
        {
            float are[8], aim[8];
            const float* xr = xs + tid * 65;
            float x0  = xr[0];
            float x32 = xr[32];
            #pragma unroll
            for (int k2 = 0; k2 < 8; ++k2) {
                // w64[256+k2] = (cos(pi k2), -sin(pi k2)) = ((-1)^k2, 0) exactly
                are[k2] = fmaf(x32, w64[256 + k2].x, x0);
                aim[k2] = 0.f;
            }
            #pragma unroll 4
            for (int n2 = 1; n2 < 32; ++n2) {
                float xa = xr[n2], xb = xr[64 - n2];
                float sum = xa + xb, dif = xa - xb;
                const float4* wv = (const float4*)(w64 + n2 * 8);
                #pragma unroll
                for (int p = 0; p < 4; ++p) {
                    float4 w = wv[p];          // (cos0,-sin0,cos1,-sin1)
                    are[p * 2]     += sum * w.x;
                    aim[p * 2]     += dif * w.y;
                    are[p * 2 + 1] += sum * w.z;
                    aim[p * 2 + 1] += dif * w.w;
                }
            }
            float2* tr = T + tid * 9;
            #pragma unroll
            for (int k2 = 0; k2 < 8; ++k2) tr[k2] = make_float2(are[k2], aim[k2]);
        }
        __syncthreads();

        // stage B: per plane p: B1[p][k1,k2] = sum_n1 T[p][n1][k2] * w32[n1][k1]
        for (int o = tid; o < 512; o += 256) {
            int p = o >> 6, k1 = (o >> 3) & 7, k2 = o & 7;
            float br = 0.f, bi = 0.f;
            const float2* tb = T + (p * 32) * 9 + k2;
            #pragma unroll 8
            for (int n1 = 0; n1 < 32; ++n1) {
                float2 tv = tb[n1 * 9];
                float2 w  = w32[n1 * 8 + k1];
                br += tv.x * w.x - tv.y * w.y;
                bi += tv.x * w.y + tv.y * w.x;
            }
            B1[o] = make_float2(br, bi);
        }
        __syncthreads();

        // stage C: accumulate over n0 with e^{-2pi i k0 n0/32}
        #pragma unroll
        for (int p = 0; p < 8; ++p) {
            int n0 = chunk * 8 + p;
            float2 b  = B1[p * 64 + m];
            float2 wA = w32[n0 * 8 + g];
            float2 wB = w32[n0 * 8 + g + 4];
            aAr += b.x * wA.x - b.y * wA.y;  aAi += b.x * wA.y + b.y * wA.x;
            aBr += b.x * wB.x - b.y * wB.y;  aBi += b.x * wB.y + b.y * wB.x;
        }
        __syncthreads();
    }

    const float sc = 1.0f / 256.0f;   // ortho: 1/sqrt(32*32*64)
    d_xsel[c * 512 + g * 64 + m]       = make_float2(aAr * sc, aAi * sc);
    d_xsel[c * 512 + (g + 4) * 64 + m] = make_float2(aBr * sc, aBi * sc);
}

// ---------------------------------------------------------------------------
// Kernel 2: complex attention + projection, y-split across two 128-thread groups.
// CTA = (bh, x-chunk of 128).  Group grp handles y in [grp*256, grp*256+256).
// Per y: a = sum_e q[e,x] k[e,y] (even/odd split accumulators: shorter rounding
// chains + 2x FMA ILP), t = ctanh(a), acc[e] += t * k[e,y].
// ctanh via the C99-robust identity with accurate primitives (tanhf/tanf, IEEE div):
//   tanh(a+ib) = (t(1+T^2) + i T(1-t^2)) / (1 + t^2 T^2),  t=tanh a, T=tan b.
// Partials reduced via smem, then the two groups split the 16-o projection:
//   Z[o,x] = (1/16384) * sum_e acc[e] * w[h,e,o,x].
// ---------------------------------------------------------------------------
__global__ void __launch_bounds__(256) attn_kernel(const float* __restrict__ wre,
                                                   const float* __restrict__ wim)
{
    extern __shared__ float smraw[];
    // phase 1: ks[grp][e][y], 2 * 16*256 float2 = 64 KB
    // phase 2 (reuse): red[2][128][33] floats = 33792 B
    float2* ks  = (float2*)smraw;
    float*  red = smraw;

    const int tid = threadIdx.x;
    const int grp = tid >> 7;        // y-half this thread accumulates
    const int t   = tid & 127;
    const int bh  = blockIdx.x >> 2;
    const int xc  = blockIdx.x & 3;
    const int h   = bh & 7;
    const int x   = xc * 128 + t;

    float qre[16], qim[16], ar[16], ai[16];
    #pragma unroll
    for (int e = 0; e < 16; ++e) {
        float2 v = d_xsel[(bh * 16 + e) * 512 + x];
        qre[e] = v.x; qim[e] = v.y;
        ar[e] = 0.f; ai[e] = 0.f;
    }

    // each group loads its own K half-tile
    float2* ksg = ks + grp * 4096;
    for (int i = t; i < 16 * 256; i += 128) {
        int e = i >> 8, y = i & 255;
        ksg[i] = d_xsel[(1024 + bh * 16 + e) * 512 + grp * 256 + y];
    }
    __syncthreads();

    #pragma unroll 2
    for (int y = 0; y < 256; ++y) {
        float2 kk[16];
        float dr0 = 0.f, di0 = 0.f, dr1 = 0.f, di1 = 0.f;
        #pragma unroll
        for (int e = 0; e < 16; e += 2) {
            kk[e]     = ksg[e * 256 + y];
            kk[e + 1] = ksg[(e + 1) * 256 + y];
            dr0 += qre[e] * kk[e].x - qim[e] * kk[e].y;
            di0 += qre[e] * kk[e].y + qim[e] * kk[e].x;
            dr1 += qre[e + 1] * kk[e + 1].x - qim[e + 1] * kk[e + 1].y;
            di1 += qre[e + 1] * kk[e + 1].y + qim[e + 1] * kk[e + 1].x;
        }
        float dr = dr0 + dr1;
        float di = di0 + di1;
        // accurate complex tanh: t=tanh(dr), T=tan(di)
        float th = tanhf(dr);
        float tn = tanf(di);
        float th2 = th * th;
        float tn2 = tn * tn;
        float rden = 1.0f / fmaf(th2, tn2, 1.0f);     // IEEE divide
        float tre = th * (1.0f + tn2) * rden;
        float tim = tn * (1.0f - th2) * rden;
        #pragma unroll
        for (int e = 0; e < 16; ++e) {
            ar[e] += tre * kk[e].x - tim * kk[e].y;
            ai[e] += tre * kk[e].y + tim * kk[e].x;
        }
    }
    __syncthreads();   // done with ks; reuse smem for reduction

    // write partial accumulators (padded rows: stride 33 -> conflict-free)
    float* row = red + (grp * 128 + t) * 33;
    #pragma unroll
    for (int e = 0; e < 16; ++e) { row[e] = ar[e]; row[16 + e] = ai[e]; }
    __syncthreads();

    // combine both halves for this x
    const float* r0 = red + t * 33;
    const float* r1 = red + (128 + t) * 33;
    float cr[16], ci[16];
    #pragma unroll
    for (int e = 0; e < 16; ++e) {
        cr[e] = r0[e]      + r1[e];
        ci[e] = r0[16 + e] + r1[16 + e];
    }

    // projection: group grp handles o in [grp*8, grp*8+8)
    const float sc = 1.0f / 16384.0f;  // / (C_IN*C_OUT)
    #pragma unroll 1
    for (int oo = 0; oo < 8; ++oo) {
        int o = grp * 8 + oo;
        float zr = 0.f, zi = 0.f;
        #pragma unroll
        for (int e = 0; e < 16; ++e) {
            float wr = wre[((h * 16 + e) * 16 + o) * 512 + x];
            float wi = wim[((h * 16 + e) * 16 + o) * 512 + x];
            zr += cr[e] * wr - ci[e] * wi;
            zi += cr[e] * wi + ci[e] * wr;
        }
        d_z[(bh * 16 + o) * 512 + x] = make_float2(zr * sc, zi * sc);
    }
}

// ---------------------------------------------------------------------------
// Kernel 3: inverse.  Symmetrization over dims(3,4) + ifft2 == Re(ifft2(A));
// final irfft of a real 8-mode half-spectrum == cosine sum.
// out[n0,n1,n2] = sum_{k2} Re( (sum_{k0,k1} Z e^{+2pi i(k0n0+k1n1)/32}) ) * ctab[k2][n2]
// ctab[k2][n2] = ((k2==0)?1:2) * cos(2pi k2 n2/64) / 256      (1/32 ifft2 * 1/8 irfft)
// ---------------------------------------------------------------------------
__global__ void __launch_bounds__(256) inv_kernel(float* __restrict__ out)
{
    extern __shared__ float sm[];
    float2* z    = (float2*)sm;            // 512
    float2* H1   = (float2*)(sm + 1024);   // 32 x 65 (padded)
    float2* twp  = (float2*)(sm + 5184);   // 32 x 8: e^{+2pi i n k/32}
    float*  R    = sm + 5696;              // 32 x 257 (padded) reals
    float*  ctab = sm + 13920;             // 8 x 64

    const int tid = threadIdx.x;
    const int c   = blockIdx.x;

    {
        int n = tid >> 3, k = tid & 7;
        float s, co;
        sincospif((float)(n * k) * (1.0f / 16.0f), &s, &co);
        twp[tid] = make_float2(co, s);
        for (int i = tid; i < 512; i += 256) {
            int k2 = i >> 6, n2 = i & 63;
            float wgt = (k2 == 0) ? (1.0f / 256.0f) : (2.0f / 256.0f);
            ctab[i] = wgt * cospif((float)(k2 * n2) * (1.0f / 32.0f));
        }
        for (int i = tid; i < 512; i += 256) z[i] = d_z[c * 512 + i];
    }
    __syncthreads();

    // I1: expand k0 -> n0
    {
        int m = tid & 63, g = tid >> 6;
        #pragma unroll
        for (int p = 0; p < 8; ++p) {
            int n0 = g * 8 + p;
            float hr = 0.f, hi = 0.f;
            #pragma unroll
            for (int k0 = 0; k0 < 8; ++k0) {
                float2 zv = z[k0 * 64 + m];
                float2 w  = twp[n0 * 8 + k0];
                hr += zv.x * w.x - zv.y * w.y;
                hi += zv.x * w.y + zv.y * w.x;
            }
            H1[n0 * 65 + m] = make_float2(hr, hi);
        }
    }
    __syncthreads();

    // I2: expand k1 -> n1, keep real part only
    {
        int n0 = tid >> 3, k2 = tid & 7;
        float2 hv[8];
        #pragma unroll
        for (int k1 = 0; k1 < 8; ++k1) hv[k1] = H1[n0 * 65 + k1 * 8 + k2];
        for (int n1 = 0; n1 < 32; ++n1) {
            float acc = 0.f;
            #pragma unroll
            for (int k1 = 0; k1 < 8; ++k1) {
                float2 w = twp[n1 * 8 + k1];
                acc += hv[k1].x * w.x - hv[k1].y * w.y;
            }
            R[n0 * 257 + n1 * 8 + k2] = acc;
        }
    }
    __syncthreads();

    // I3: cosine expansion k2 -> n2, vectorized float4 stores
    {
        float* og = out + ((size_t)c << 16);
        int rsub = tid >> 4;           // 0..15 (row within pass)
        int n2b  = (tid & 15) * 4;
        for (int it = 0; it < 64; ++it) {
            int row = it * 16 + rsub;  // (n0,n1) row 0..1023
            int n0 = row >> 5, n1 = row & 31;
            const float* rr = R + n0 * 257 + n1 * 8;
            float4 o = make_float4(0.f, 0.f, 0.f, 0.f);
            #pragma unroll
            for (int k2 = 0; k2 < 8; ++k2) {
                float rv = rr[k2];
                float4 cv = *(const float4*)(ctab + k2 * 64 + n2b);
                o.x += rv * cv.x; o.y += rv * cv.y;
                o.z += rv * cv.z; o.w += rv * cv.w;
            }
            *(float4*)(og + row * 64 + n2b) = o;
        }
    }
}

// ---------------------------------------------------------------------------
extern "C" void kernel_launch(void* const* d_in, const int* in_sizes, int n_in,
                              void* d_out, int out_size)
{
    const float* q   = (const float*)d_in[0];
    const float* k   = (const float*)d_in[1];
    const float* wre = (const float*)d_in[2];
    const float* wim = (const float*)d_in[3];
    float* out = (float*)d_out;

    cudaFuncSetAttribute(fwd_dft_kernel, cudaFuncAttributeMaxDynamicSharedMemorySize, 96 * 1024);
    cudaFuncSetAttribute(attn_kernel,    cudaFuncAttributeMaxDynamicSharedMemorySize, 68 * 1024);
    cudaFuncSetAttribute(inv_kernel,     cudaFuncAttributeMaxDynamicSharedMemorySize, 60 * 1024);

    fwd_dft_kernel<<<2048, 256, 95232>>>(q, k);
    attn_kernel<<<256, 256, 65536>>>(wre, wim);
    inv_kernel<<<1024, 256, 57728>>>(out);
}

// round 16
// speedup vs baseline: 1.0117x; 1.0117x over previous
#include <cuda_runtime.h>

// scratch (static device globals - no allocation allowed)
__device__ float2 d_xsel[2048 * 512];   // fwd DFT modes: ch 0..1023 = q, 1024..2047 = k
__device__ float2 d_z[1024 * 512];      // xqkvw / 16384, per (b,h,o) channel

// ---------------------------------------------------------------------------
// Kernel 1: truncated forward DFT (ortho).  One CTA per channel (2048 CTAs).
// X[k0,k1,k2] = (1/256) * sum_{n0,n1,n2} x[n0,n1,n2] e^{-2pi i(k0 n0/32 + k1 n1/32 + k2 n2/64)}
// separable: dim2 (64->8, real-input symmetry halves it) -> dim1 (32->8) -> dim0 (32->8),
// processed in 8 chunks of 4 n0-planes (small smem -> 4 CTAs/SM residency).
// ---------------------------------------------------------------------------
__global__ void __launch_bounds__(256) fwd_dft_kernel(const float* __restrict__ q,
                                                      const float* __restrict__ kin)
{
    extern __shared__ float sm[];
    float*  xs  = sm;                       // 128 rows x 65 (padded) = 8320 floats
    float2* T   = (float2*)(sm + 8320);     // 128 x 9 (padded)      = 1152 float2
    float2* B1  = T + 1152;                 // 4 x 64                = 256 float2
    float2* w64 = B1 + 256;                 // 64 x 8 twiddles       = 512 float2 (16B aligned)
    float2* w32 = w64 + 512;                // 32 x 8 twiddles       = 256 float2
    // total = 12672 floats = 50688 bytes -> 4 CTAs/SM

    const int tid = threadIdx.x;
    const int c   = blockIdx.x;
    const float* src = (c < 1024) ? (q + (size_t)c * 65536)
                                  : (kin + (size_t)(c - 1024) * 65536);

    // twiddles: w64[n*8+k] = exp(-2pi i n k / 64), w32[n*8+k] = exp(-2pi i n k / 32)
    {
        float s, co;
        int n = tid >> 3, k = tid & 7;
        sincospif((float)(n * k) * (1.0f / 32.0f), &s, &co);
        w64[tid] = make_float2(co, -s);
        int t2 = tid + 256;
        n = t2 >> 3; k = t2 & 7;
        sincospif((float)(n * k) * (1.0f / 32.0f), &s, &co);
        w64[t2] = make_float2(co, -s);
        n = tid >> 3; k = tid & 7;
        sincospif((float)(n * k) * (1.0f / 16.0f), &s, &co);
        w32[tid] = make_float2(co, -s);
    }
    __syncthreads();

    const int m = tid & 63;     // k1*8 + k2
    const int g = tid >> 6;     // owns k0 = g and g+4
    float aAr = 0.f, aAi = 0.f, aBr = 0.f, aBi = 0.f;

    for (int chunk = 0; chunk < 8; ++chunk) {
        // load 4 n0-planes (8192 floats) coalesced into padded smem rows
        const float* s0 = src + chunk * 8192;
        for (int i = tid * 4; i < 8192; i += 1024) {
            float4 v = *(const float4*)(s0 + i);
            int row = i >> 6, col = i & 63;
            float* d = xs + row * 65 + col;
            d[0] = v.x; d[1] = v.y; d[2] = v.z; d[3] = v.w;
        }
        __syncthreads();

        // stage A: 2 threads per row (half = tid>>7 owns 4 k2 modes).
        // 8 k2 modes over n2, real-input symmetry: pair n2 with 64-n2.
        // half is warp-uniform -> twiddle LDS.128 broadcasts stay conflict-free.
        {
            const int row  = tid & 127;
            const int half = tid >> 7;          // 0: k2 0-3, 1: k2 4-7
            float are[4], aim[4];
            const float* xr = xs + row * 65;
            float x0  = xr[0];
            float x32 = xr[32];
            #pragma unroll
            for (int kk = 0; kk < 4; ++kk) {
                // w64[256+k2] = ((-1)^k2, 0) exactly
                are[kk] = fmaf(x32, w64[256 + half * 4 + kk].x, x0);
                aim[kk] = 0.f;
            }
            #pragma unroll 4
            for (int n2 = 1; n2 < 32; ++n2) {
                float xa = xr[n2], xb = xr[64 - n2];
                float sum = xa + xb, dif = xa - xb;
                const float4* wv = (const float4*)(w64 + n2 * 8 + half * 4);
                #pragma unroll
                for (int p = 0; p < 2; ++p) {
                    float4 w = wv[p];          // (cos0,-sin0,cos1,-sin1)
                    are[p * 2]     += sum * w.x;
                    aim[p * 2]     += dif * w.y;
                    are[p * 2 + 1] += sum * w.z;
                    aim[p * 2 + 1] += dif * w.w;
                }
            }
            float2* tr = T + row * 9 + half * 4;
            #pragma unroll
            for (int kk = 0; kk < 4; ++kk) tr[kk] = make_float2(are[kk], aim[kk]);
        }
        __syncthreads();

        // stage B: 256 outputs (4 planes x 64 modes) = 1 per thread:
        // B1[p][k1,k2] = sum_n1 T[p][n1][k2] * w32[n1][k1]
        {
            int p = tid >> 6, k1 = (tid >> 3) & 7, k2 = tid & 7;
            float br = 0.f, bi = 0.f;
            const float2* tb = T + (p * 32) * 9 + k2;
            #pragma unroll 8
            for (int n1 = 0; n1 < 32; ++n1) {
                float2 tv = tb[n1 * 9];
                float2 w  = w32[n1 * 8 + k1];
                br += tv.x * w.x - tv.y * w.y;
                bi += tv.x * w.y + tv.y * w.x;
            }
            B1[tid] = make_float2(br, bi);
        }
        __syncthreads();

        // stage C: accumulate over n0 with e^{-2pi i k0 n0/32}
        // (chunk*4+p sweeps n0 = 0..31 in order -> bit-identical to before)
        #pragma unroll
        for (int p = 0; p < 4; ++p) {
            int n0 = chunk * 4 + p;
            float2 b  = B1[p * 64 + m];
            float2 wA = w32[n0 * 8 + g];
            float2 wB = w32[n0 * 8 + g + 4];
            aAr += b.x * wA.x - b.y * wA.y;  aAi += b.x * wA.y + b.y * wA.x;
            aBr += b.x * wB.x - b.y * wB.y;  aBi += b.x * wB.y + b.y * wB.x;
        }
        __syncthreads();
    }

    const float sc = 1.0f / 256.0f;   // ortho: 1/sqrt(32*32*64)
    d_xsel[c * 512 + g * 64 + m]       = make_float2(aAr * sc, aAi * sc);
    d_xsel[c * 512 + (g + 4) * 64 + m] = make_float2(aBr * sc, aBi * sc);
}

// ---------------------------------------------------------------------------
// Kernel 2: complex attention + projection, y-split across two 128-thread groups.
// CTA = (bh, x-chunk of 128).  Group grp handles y in [grp*256, grp*256+256).
// Per y: a = sum_e q[e,x] k[e,y] (even/odd split accumulators: shorter rounding
// chains + 2x FMA ILP), t = ctanh(a), acc[e] += t * k[e,y].
// ctanh via the C99-robust identity with accurate primitives (tanhf/tanf, IEEE div):
//   tanh(a+ib) = (t(1+T^2) + i T(1-t^2)) / (1 + t^2 T^2),  t=tanh a, T=tan b.
// Partials reduced via smem, then the two groups split the 16-o projection:
//   Z[o,x] = (1/16384) * sum_e acc[e] * w[h,e,o,x].
// ---------------------------------------------------------------------------
__global__ void __launch_bounds__(256) attn_kernel(const float* __restrict__ wre,
                                                   const float* __restrict__ wim)
{
    extern __shared__ float smraw[];
    // phase 1: ks[grp][e][y], 2 * 16*256 float2 = 64 KB
    // phase 2 (reuse): red[2][128][33] floats = 33792 B
    float2* ks  = (float2*)smraw;
    float*  red = smraw;

    const int tid = threadIdx.x;
    const int grp = tid >> 7;        // y-half this thread accumulates
    const int t   = tid & 127;
    const int bh  = blockIdx.x >> 2;
    const int xc  = blockIdx.x & 3;
    const int h   = bh & 7;
    const int x   = xc * 128 + t;

    float qre[16], qim[16], ar[16], ai[16];
    #pragma unroll
    for (int e = 0; e < 16; ++e) {
        float2 v = d_xsel[(bh * 16 + e) * 512 + x];
        qre[e] = v.x; qim[e] = v.y;
        ar[e] = 0.f; ai[e] = 0.f;
    }

    // each group loads its own K half-tile
    float2* ksg = ks + grp * 4096;
    for (int i = t; i < 16 * 256; i += 128) {
        int e = i >> 8, y = i & 255;
        ksg[i] = d_xsel[(1024 + bh * 16 + e) * 512 + grp * 256 + y];
    }
    __syncthreads();

    #pragma unroll 2
    for (int y = 0; y < 256; ++y) {
        float2 kk[16];
        float dr0 = 0.f, di0 = 0.f, dr1 = 0.f, di1 = 0.f;
        #pragma unroll
        for (int e = 0; e < 16; e += 2) {
            kk[e]     = ksg[e * 256 + y];
            kk[e + 1] = ksg[(e + 1) * 256 + y];
            dr0 += qre[e] * kk[e].x - qim[e] * kk[e].y;
            di0 += qre[e] * kk[e].y + qim[e] * kk[e].x;
            dr1 += qre[e + 1] * kk[e + 1].x - qim[e + 1] * kk[e + 1].y;
            di1 += qre[e + 1] * kk[e + 1].y + qim[e + 1] * kk[e + 1].x;
        }
        float dr = dr0 + dr1;
        float di = di0 + di1;
        // accurate complex tanh: t=tanh(dr), T=tan(di)
        float th = tanhf(dr);
        float tn = tanf(di);
        float th2 = th * th;
        float tn2 = tn * tn;
        float rden = 1.0f / fmaf(th2, tn2, 1.0f);     // IEEE divide
        float tre = th * (1.0f + tn2) * rden;
        float tim = tn * (1.0f - th2) * rden;
        #pragma unroll
        for (int e = 0; e < 16; ++e) {
            ar[e] += tre * kk[e].x - tim * kk[e].y;
            ai[e] += tre * kk[e].y + tim * kk[e].x;
        }
    }
    __syncthreads();   // done with ks; reuse smem for reduction

    // write partial accumulators (padded rows: stride 33 -> conflict-free)
    float* row = red + (grp * 128 + t) * 33;
    #pragma unroll
    for (int e = 0; e < 16; ++e) { row[e] = ar[e]; row[16 + e] = ai[e]; }
    __syncthreads();

    // combine both halves for this x
    const float* r0 = red + t * 33;
    const float* r1 = red + (128 + t) * 33;
    float cr[16], ci[16];
    #pragma unroll
    for (int e = 0; e < 16; ++e) {
        cr[e] = r0[e]      + r1[e];
        ci[e] = r0[16 + e] + r1[16 + e];
    }

    // projection: group grp handles o in [grp*8, grp*8+8)
    const float sc = 1.0f / 16384.0f;  // / (C_IN*C_OUT)
    #pragma unroll 1
    for (int oo = 0; oo < 8; ++oo) {
        int o = grp * 8 + oo;
        float zr = 0.f, zi = 0.f;
        #pragma unroll
        for (int e = 0; e < 16; ++e) {
            float wr = wre[((h * 16 + e) * 16 + o) * 512 + x];
            float wi = wim[((h * 16 + e) * 16 + o) * 512 + x];
            zr += cr[e] * wr - ci[e] * wi;
            zi += cr[e] * wi + ci[e] * wr;
        }
        d_z[(bh * 16 + o) * 512 + x] = make_float2(zr * sc, zi * sc);
    }
}

// ---------------------------------------------------------------------------
// Kernel 3: inverse.  Symmetrization over dims(3,4) + ifft2 == Re(ifft2(A));
// final irfft of a real 8-mode half-spectrum == cosine sum.
// out[n0,n1,n2] = sum_{k2} Re( (sum_{k0,k1} Z e^{+2pi i(k0n0+k1n1)/32}) ) * ctab[k2][n2]
// ctab[k2][n2] = ((k2==0)?1:2) * cos(2pi k2 n2/64) / 256      (1/32 ifft2 * 1/8 irfft)
// ---------------------------------------------------------------------------
__global__ void __launch_bounds__(256) inv_kernel(float* __restrict__ out)
{
    extern __shared__ float sm[];
    float2* z    = (float2*)sm;            // 512
    float2* H1   = (float2*)(sm + 1024);   // 32 x 65 (padded)
    float2* twp  = (float2*)(sm + 5184);   // 32 x 8: e^{+2pi i n k/32}
    float*  R    = sm + 5696;              // 32 x 257 (padded) reals
    float*  ctab = sm + 13920;             // 8 x 64

    const int tid = threadIdx.x;
    const int c   = blockIdx.x;

    {
        int n = tid >> 3, k = tid & 7;
        float s, co;
        sincospif((float)(n * k) * (1.0f / 16.0f), &s, &co);
        twp[tid] = make_float2(co, s);
        for (int i = tid; i < 512; i += 256) {
            int k2 = i >> 6, n2 = i & 63;
            float wgt = (k2 == 0) ? (1.0f / 256.0f) : (2.0f / 256.0f);
            ctab[i] = wgt * cospif((float)(k2 * n2) * (1.0f / 32.0f));
        }
        for (int i = tid; i < 512; i += 256) z[i] = d_z[c * 512 + i];
    }
    __syncthreads();

    // I1: expand k0 -> n0
    {
        int m = tid & 63, g = tid >> 6;
        #pragma unroll
        for (int p = 0; p < 8; ++p) {
            int n0 = g * 8 + p;
            float hr = 0.f, hi = 0.f;
            #pragma unroll
            for (int k0 = 0; k0 < 8; ++k0) {
                float2 zv = z[k0 * 64 + m];
                float2 w  = twp[n0 * 8 + k0];
                hr += zv.x * w.x - zv.y * w.y;
                hi += zv.x * w.y + zv.y * w.x;
            }
            H1[n0 * 65 + m] = make_float2(hr, hi);
        }
    }
    __syncthreads();

    // I2: expand k1 -> n1, keep real part only
    {
        int n0 = tid >> 3, k2 = tid & 7;
        float2 hv[8];
        #pragma unroll
        for (int k1 = 0; k1 < 8; ++k1) hv[k1] = H1[n0 * 65 + k1 * 8 + k2];
        for (int n1 = 0; n1 < 32; ++n1) {
            float acc = 0.f;
            #pragma unroll
            for (int k1 = 0; k1 < 8; ++k1) {
                float2 w = twp[n1 * 8 + k1];
                acc += hv[k1].x * w.x - hv[k1].y * w.y;
            }
            R[n0 * 257 + n1 * 8 + k2] = acc;
        }
    }
    __syncthreads();

    // I3: cosine expansion k2 -> n2, vectorized float4 stores
    {
        float* og = out + ((size_t)c << 16);
        int rsub = tid >> 4;           // 0..15 (row within pass)
        int n2b  = (tid & 15) * 4;
        for (int it = 0; it < 64; ++it) {
            int row = it * 16 + rsub;  // (n0,n1) row 0..1023
            int n0 = row >> 5, n1 = row & 31;
            const float* rr = R + n0 * 257 + n1 * 8;
            float4 o = make_float4(0.f, 0.f, 0.f, 0.f);
            #pragma unroll
            for (int k2 = 0; k2 < 8; ++k2) {
                float rv = rr[k2];
                float4 cv = *(const float4*)(ctab + k2 * 64 + n2b);
                o.x += rv * cv.x; o.y += rv * cv.y;
                o.z += rv * cv.z; o.w += rv * cv.w;
            }
            *(float4*)(og + row * 64 + n2b) = o;
        }
    }
}

// ---------------------------------------------------------------------------
extern "C" void kernel_launch(void* const* d_in, const int* in_sizes, int n_in,
                              void* d_out, int out_size)
{
    const float* q   = (const float*)d_in[0];
    const float* k   = (const float*)d_in[1];
    const float* wre = (const float*)d_in[2];
    const float* wim = (const float*)d_in[3];
    float* out = (float*)d_out;

    cudaFuncSetAttribute(fwd_dft_kernel, cudaFuncAttributeMaxDynamicSharedMemorySize, 52 * 1024);
    cudaFuncSetAttribute(attn_kernel,    cudaFuncAttributeMaxDynamicSharedMemorySize, 68 * 1024);
    cudaFuncSetAttribute(inv_kernel,     cudaFuncAttributeMaxDynamicSharedMemorySize, 60 * 1024);

    fwd_dft_kernel<<<2048, 256, 50688>>>(q, k);
    attn_kernel<<<256, 256, 65536>>>(wre, wim);
    inv_kernel<<<1024, 256, 57728>>>(out);
}